// round 4
// baseline (speedup 1.0000x reference)
#include <cuda_runtime.h>
#include <cuda_fp16.h>
#include <cstdint>

#define NN 1000000
#define EE 1000000
#define CC 64
#define ROW 65           // C+1 floats per poss_edge row
#define G1 592           // kernel-1 grid: 4 blocks/SM single wave
#define NODE_B 32
#define SCALAR_B 96
#define G2 1184
#define GROUPS (EE / 4)  // 4 edges per warp-iteration

// fp16 copies of poss_edge: cols 0..63 packed (128 B/row, line-aligned), col 64 split out
__device__ __half2 g_A[(size_t)NN * 32];   // 128 MB scratch
__device__ __half  g_PL[NN];               // 2 MB, L2-resident
// Accumulators: 0=sum(mask*logp) 1=sum(mask) 2=sqdiff 3=sum(intrust) 4=raw 5=S
__device__ double g_acc[6];

__global__ void k_zero() {
    if (threadIdx.x < 6) g_acc[threadIdx.x] = 0.0;
}

__device__ __forceinline__ void block_reduce_add(
    double v0, double v1, double v2, double v3, double v4, double v5)
{
    double vals[6] = {v0, v1, v2, v3, v4, v5};
    const int lane = threadIdx.x & 31;
    const int wib = threadIdx.x >> 5;
    #pragma unroll
    for (int k = 0; k < 6; k++) {
        double v = vals[k];
        #pragma unroll
        for (int o = 16; o; o >>= 1) v += __shfl_xor_sync(0xffffffffu, v, o);
        vals[k] = v;
    }
    __shared__ double sh[8][6];
    if (lane == 0) {
        #pragma unroll
        for (int k = 0; k < 6; k++) sh[wib][k] = vals[k];
    }
    __syncthreads();
    if (threadIdx.x == 0) {
        #pragma unroll
        for (int k = 0; k < 6; k++) {
            double t = 0.0;
            for (int w = 0; w < 8; w++) t += sh[w][k];
            atomicAdd(&g_acc[k], t);
        }
    }
}

// ---- kernel 1: fp16 conversion + node loss + per-edge scalar terms ----
__global__ void __launch_bounds__(256, 4) k_prep(
    const float* __restrict__ pn,
    const float* __restrict__ pe,
    const int* __restrict__ gt,
    const uint8_t* __restrict__ mask,
    const int* __restrict__ edges)
{
    const int bid = blockIdx.x;
    const int lane = threadIdx.x & 31;
    const int2* __restrict__ edges2 = (const int2*)edges;

    float f_logp = 0.0f, f_intr = 0.0f, f_raw = 0.0f;
    int i_mask = 0, i_S = 0;

    if (bid < NODE_B) {
        // ---- node loss: ILP-4 thread-per-node ----
        const int ltid = bid * 256 + threadIdx.x;
        const int lnth = NODE_B * 256;
        int i = ltid;
        for (; i + 3 * lnth < NN; i += 4 * lnth) {
            int idx[4]; unsigned m[4]; int g[4];
            #pragma unroll
            for (int j = 0; j < 4; j++) idx[j] = i + j * lnth;
            #pragma unroll
            for (int j = 0; j < 4; j++) m[j] = mask[idx[j]];
            #pragma unroll
            for (int j = 0; j < 4; j++) g[j] = gt[idx[j]];
            float p[4];
            #pragma unroll
            for (int j = 0; j < 4; j++)
                p[j] = m[j] ? __ldcs(&pn[(size_t)idx[j] * CC + g[j]]) : 1.0f;
            #pragma unroll
            for (int j = 0; j < 4; j++)
                if (m[j]) { f_logp += __logf(p[j]); i_mask++; }
        }
        for (; i < NN; i += lnth) {
            if (mask[i]) {
                f_logp += __logf(__ldcs(&pn[(size_t)i * CC + gt[i]]));
                i_mask++;
            }
        }
    } else if (bid < NODE_B + SCALAR_B) {
        // ---- per-edge scalar terms: ILP-4 thread-per-edge ----
        const int ltid = (bid - NODE_B) * 256 + threadIdx.x;
        const int lnth = SCALAR_B * 256;
        int e = ltid;
        for (; e + 3 * lnth < EE; e += 4 * lnth) {
            int ei[4]; int2 ev[4]; float pl[4];
            unsigned m0[4], m1[4]; int g0[4], g1[4];
            #pragma unroll
            for (int j = 0; j < 4; j++) ei[j] = e + j * lnth;
            #pragma unroll
            for (int j = 0; j < 4; j++) ev[j] = edges2[ei[j]];
            #pragma unroll
            for (int j = 0; j < 4; j++) pl[j] = __ldcs(&pe[(size_t)ei[j] * ROW + CC]);
            #pragma unroll
            for (int j = 0; j < 4; j++) { m0[j] = mask[ev[j].x]; m1[j] = mask[ev[j].y]; }
            #pragma unroll
            for (int j = 0; j < 4; j++) { g0[j] = gt[ev[j].x]; g1[j] = gt[ev[j].y]; }
            #pragma unroll
            for (int j = 0; j < 4; j++) {
                f_intr += pl[j];
                if (m0[j] | m1[j]) {
                    i_S++;
                    float c;
                    if (m0[j] & m1[j]) {
                        c = (g0[j] == g1[j])
                              ? __logf(__ldcs(&pe[(size_t)ei[j] * ROW + g0[j]]))
                              : __logf(pl[j]);
                    } else {
                        int g = m0[j] ? g0[j] : g1[j];
                        c = __logf(pl[j] + __ldcs(&pe[(size_t)ei[j] * ROW + g]));
                    }
                    f_raw -= c;
                }
            }
        }
        for (; e < EE; e += lnth) {
            int2 ev = edges2[e];
            float pl = __ldcs(&pe[(size_t)e * ROW + CC]);
            f_intr += pl;
            unsigned m0 = mask[ev.x], m1 = mask[ev.y];
            if (m0 | m1) {
                i_S++;
                float c;
                if (m0 & m1) {
                    int ga = gt[ev.x], gb = gt[ev.y];
                    c = (ga == gb) ? __logf(__ldcs(&pe[(size_t)e * ROW + ga])) : __logf(pl);
                } else {
                    int g = m0 ? gt[ev.x] : gt[ev.y];
                    c = __logf(pl + __ldcs(&pe[(size_t)e * ROW + g]));
                }
                f_raw -= c;
            }
        }
    } else {
        // ---- fp32 -> fp16 conversion: warp-per-row, 2 rows per iteration ----
        const int cw = (bid - NODE_B - SCALAR_B) * 8 + (threadIdx.x >> 5);
        const int ncw = (G1 - NODE_B - SCALAR_B) * 8;  // conversion warps
        for (int r = cw * 2; r < NN; r += ncw * 2) {
            const float* __restrict__ s0 = pe + (size_t)r * ROW;
            const float* __restrict__ s1 = pe + (size_t)(r + 1) * ROW;
            // batch all loads (cols 2l, 2l+1 of both rows) before storing
            float a0 = __ldcs(&s0[2 * lane]);
            float a1 = __ldcs(&s0[2 * lane + 1]);
            float b0 = __ldcs(&s1[2 * lane]);
            float b1 = __ldcs(&s1[2 * lane + 1]);
            float t0 = 0.0f, t1 = 0.0f;
            if (lane == 31) { t0 = __ldcs(&s0[CC]); t1 = __ldcs(&s1[CC]); }
            g_A[(size_t)r * 32 + lane]       = __floats2half2_rn(a0, a1);
            g_A[(size_t)(r + 1) * 32 + lane] = __floats2half2_rn(b0, b1);
            if (lane == 31) {
                g_PL[r]     = __float2half_rn(t0);
                g_PL[r + 1] = __float2half_rn(t1);
            }
        }
    }

    block_reduce_add((double)f_logp, (double)i_mask, 0.0,
                     (double)f_intr, (double)f_raw, (double)i_S);
}

// ---- kernel 2: sqdiff over the fp16 table, warp-per-4-edges ----
__global__ void __launch_bounds__(256, 6) k_sq(const int* __restrict__ edges)
{
    const int lane = threadIdx.x & 31;
    const int gw = (blockIdx.x * 256 + threadIdx.x) >> 5;
    const int nw = (G2 * 256) >> 5;
    const int2* __restrict__ edges2 = (const int2*)edges;

    float f_sq = 0.0f;

    for (int g = gw; g < GROUPS; g += nw) {
        const int e0 = g * 4;
        int2 ev[4];
        #pragma unroll
        for (int j = 0; j < 4; j++) ev[j] = __ldcs(&edges2[e0 + j]);

        // issue all 8 row loads (one aligned 128B LDG each) before consuming
        __half2 ax[4], ay[4];
        #pragma unroll
        for (int j = 0; j < 4; j++) {
            ax[j] = g_A[(size_t)ev[j].x * 32 + lane];
            ay[j] = g_A[(size_t)ev[j].y * 32 + lane];
        }
        // col-64 term from the 2MB L2-resident array: lane j handles edge j
        float dpl = 0.0f;
        if (lane < 4) {
            float px = __half2float(g_PL[ev[lane].x]);
            float py = __half2float(g_PL[ev[lane].y]);
            dpl = px - py;
        }

        float s = dpl * dpl;
        #pragma unroll
        for (int j = 0; j < 4; j++) {
            float2 fa = __half22float2(ax[j]);
            float2 fb = __half22float2(ay[j]);
            float d0 = fa.x - fb.x;
            float d1 = fa.y - fb.y;
            s += d0 * d0 + d1 * d1;
        }
        f_sq += s;
    }

    block_reduce_add(0.0, 0.0, (double)f_sq, 0.0, 0.0, 0.0);
}

__global__ void k_final(float* __restrict__ out) {
    double loss = -g_acc[0] / g_acc[1];
    double semi = 0.5 * ((double)EE - g_acc[3]) * g_acc[2];   // SEMI_LAMBDA = 0.5
    double S    = g_acc[5];
    double edge = g_acc[4] / (S * S);                          // EDGE_LAMBDA^2 = 1
    out[0] = (float)(loss + semi + edge);
}

extern "C" void kernel_launch(void* const* d_in, const int* in_sizes, int n_in,
                              void* d_out, int out_size) {
    const float*   pn    = (const float*)d_in[0];
    const float*   pe    = (const float*)d_in[1];
    const int*     gt    = (const int*)d_in[2];
    const uint8_t* mask  = (const uint8_t*)d_in[3];
    const int*     edges = (const int*)d_in[4];
    float* out = (float*)d_out;

    k_zero<<<1, 32>>>();
    k_prep<<<G1, 256>>>(pn, pe, gt, mask, edges);
    k_sq<<<G2, 256>>>(edges);
    k_final<<<1, 1>>>(out);
}

// round 6
// speedup vs baseline: 1.4386x; 1.4386x over previous
#include <cuda_runtime.h>
#include <cstdint>

#define NN 1000000
#define EE 1000000
#define CC 64
#define ROW 65           // C+1 floats per poss_edge row
#define ROWB 260         // row stride in bytes
#define GRID 592         // 4 blocks/SM * 148 SMs -> single wave
#define NODE_B 64
#define SCALAR_B 160
#define GROUPS (EE / 4)  // 250000 groups of 4 edges
#define CHUNK 128        // groups per steal
#define NCHUNK ((GROUPS + CHUNK - 1) / CHUNK)

// Per-block partials: [block][0..5] = logp, maskN, sq, intr, raw, S
// Overwritten every launch -> no zeroing needed for these.
__device__ double g_part[GRID][6];
__device__ int g_counter;

__global__ void k_zero() {
    if (threadIdx.x == 0) g_counter = 0;
}

__global__ void __launch_bounds__(256, 4) k_main(
    const float* __restrict__ pn,
    const float* __restrict__ pe,
    const int* __restrict__ gt,
    const uint8_t* __restrict__ mask,
    const int* __restrict__ edges)
{
    const int bid = blockIdx.x;
    const int lane = threadIdx.x & 31;
    const int wib = threadIdx.x >> 5;
    const int2* __restrict__ edges2 = (const int2*)edges;
    const char* __restrict__ peb = (const char*)pe;

    float f_logp = 0.0f, f_intr = 0.0f, f_raw = 0.0f, f_sq = 0.0f;
    int i_mask = 0, i_S = 0;

    if (bid < NODE_B) {
        // ---- node loss: ILP-4 thread-per-node ----
        const int ltid = bid * 256 + threadIdx.x;
        const int lnth = NODE_B * 256;
        int i = ltid;
        for (; i + 3 * lnth < NN; i += 4 * lnth) {
            int idx[4]; unsigned m[4]; int g[4];
            #pragma unroll
            for (int j = 0; j < 4; j++) idx[j] = i + j * lnth;
            #pragma unroll
            for (int j = 0; j < 4; j++) m[j] = mask[idx[j]];
            #pragma unroll
            for (int j = 0; j < 4; j++) g[j] = gt[idx[j]];
            float p[4];
            #pragma unroll
            for (int j = 0; j < 4; j++)
                p[j] = m[j] ? __ldcs(&pn[(size_t)idx[j] * CC + g[j]]) : 1.0f;
            #pragma unroll
            for (int j = 0; j < 4; j++)
                if (m[j]) { f_logp += __logf(p[j]); i_mask++; }
        }
        for (; i < NN; i += lnth) {
            if (mask[i]) {
                f_logp += __logf(__ldcs(&pn[(size_t)i * CC + gt[i]]));
                i_mask++;
            }
        }
    } else if (bid < NODE_B + SCALAR_B) {
        // ---- per-edge scalar terms: ILP-4 thread-per-edge ----
        const int ltid = (bid - NODE_B) * 256 + threadIdx.x;
        const int lnth = SCALAR_B * 256;
        int e = ltid;
        for (; e + 3 * lnth < EE; e += 4 * lnth) {
            int ei[4]; int2 ev[4]; float pl[4];
            unsigned m0[4], m1[4]; int g0[4], g1[4];
            #pragma unroll
            for (int j = 0; j < 4; j++) ei[j] = e + j * lnth;
            #pragma unroll
            for (int j = 0; j < 4; j++) ev[j] = edges2[ei[j]];
            #pragma unroll
            for (int j = 0; j < 4; j++) pl[j] = pe[(size_t)ei[j] * ROW + CC];
            #pragma unroll
            for (int j = 0; j < 4; j++) { m0[j] = mask[ev[j].x]; m1[j] = mask[ev[j].y]; }
            #pragma unroll
            for (int j = 0; j < 4; j++) { g0[j] = gt[ev[j].x]; g1[j] = gt[ev[j].y]; }
            #pragma unroll
            for (int j = 0; j < 4; j++) {
                f_intr += pl[j];
                if (m0[j] | m1[j]) {
                    i_S++;
                    float c;
                    if (m0[j] & m1[j]) {
                        c = (g0[j] == g1[j])
                              ? __logf(pe[(size_t)ei[j] * ROW + g0[j]])
                              : __logf(pl[j]);
                    } else {
                        int g = m0[j] ? g0[j] : g1[j];
                        c = __logf(pl[j] + pe[(size_t)ei[j] * ROW + g]);
                    }
                    f_raw -= c;
                }
            }
        }
        for (; e < EE; e += lnth) {
            int2 ev = edges2[e];
            float pl = pe[(size_t)e * ROW + CC];
            f_intr += pl;
            unsigned m0 = mask[ev.x], m1 = mask[ev.y];
            if (m0 | m1) {
                i_S++;
                float c;
                if (m0 & m1) {
                    int ga = gt[ev.x], gb = gt[ev.y];
                    c = (ga == gb) ? __logf(pe[(size_t)e * ROW + ga]) : __logf(pl);
                } else {
                    int g = m0 ? gt[ev.x] : gt[ev.y];
                    c = __logf(pl + pe[(size_t)e * ROW + g]);
                }
                f_raw -= c;
            }
        }
    }

    // ---- sqdiff: warp-per-4-edges, work-stolen chunks, pipelined prefetch ----
    __shared__ int s_chunk;
    for (;;) {
        if (threadIdx.x == 0) s_chunk = atomicAdd(&g_counter, 1);
        __syncthreads();
        const int c = s_chunk;
        __syncthreads();
        if (c >= NCHUNK) break;
        const int gbeg = c * CHUNK;
        const int gend = (gbeg + CHUNK < GROUPS) ? gbeg + CHUNK : GROUPS;

        int g = gbeg + wib;
        if (g >= gend) continue;

        // prologue: prefetch first group's edges
        int2 evn[4];
        #pragma unroll
        for (int j = 0; j < 4; j++) evn[j] = __ldg(&edges2[g * 4 + j]);

        while (g < gend) {
            int2 ev[4];
            #pragma unroll
            for (int j = 0; j < 4; j++) ev[j] = evn[j];
            const int gn = g + 8;

            // 32-bit byte offsets into the row table
            unsigned oa[4], ob[4];
            #pragma unroll
            for (int j = 0; j < 4; j++) {
                oa[j] = (unsigned)ev[j].x * ROWB;
                ob[j] = (unsigned)ev[j].y * ROWB;
            }

            // issue all 16 gather loads before consuming any
            float va[4], wa[4], vb[4], wb[4];
            #pragma unroll
            for (int j = 0; j < 4; j++) {
                const float* ra = (const float*)(peb + oa[j]);
                const float* rb = (const float*)(peb + ob[j]);
                va[j] = ra[lane];
                wa[j] = ra[lane + 32];
                vb[j] = rb[lane];
                wb[j] = rb[lane + 32];
            }
            // col-64 residual: lane j handles edge j
            float ca = 0.0f, cb = 0.0f;
            if (lane < 4) {
                ca = *(const float*)(peb + oa[lane] + CC * 4);
                cb = *(const float*)(peb + ob[lane] + CC * 4);
            }

            // prefetch NEXT group's edges while the 18 loads above are in flight
            if (gn < gend) {
                #pragma unroll
                for (int j = 0; j < 4; j++) evn[j] = __ldg(&edges2[gn * 4 + j]);
            }

            float s = 0.0f;
            #pragma unroll
            for (int j = 0; j < 4; j++) {
                float d0 = va[j] - vb[j];
                float d1 = wa[j] - wb[j];
                s += d0 * d0 + d1 * d1;
            }
            if (lane < 4) {
                float d2 = ca - cb;
                s += d2 * d2;
            }
            f_sq += s;
            g = gn;
        }
    }

    // ---- block reduction -> per-block partial slot (no atomics) ----
    double vals[6] = {(double)f_logp, (double)i_mask, (double)f_sq,
                      (double)f_intr, (double)f_raw,  (double)i_S};
    #pragma unroll
    for (int k = 0; k < 6; k++) {
        double v = vals[k];
        #pragma unroll
        for (int o = 16; o; o >>= 1) v += __shfl_xor_sync(0xffffffffu, v, o);
        vals[k] = v;
    }
    __shared__ double sh[8][6];
    if (lane == 0) {
        #pragma unroll
        for (int k = 0; k < 6; k++) sh[wib][k] = vals[k];
    }
    __syncthreads();
    if (threadIdx.x < 6) {
        double t = 0.0;
        #pragma unroll
        for (int w = 0; w < 8; w++) t += sh[w][threadIdx.x];
        g_part[bid][threadIdx.x] = t;
    }
}

__global__ void __launch_bounds__(192) k_final(float* __restrict__ out) {
    // warp k reduces accumulator k over all blocks
    const int k = threadIdx.x >> 5;
    const int lane = threadIdx.x & 31;
    double t = 0.0;
    for (int b = lane; b < GRID; b += 32) t += g_part[b][k];
    #pragma unroll
    for (int o = 16; o; o >>= 1) t += __shfl_xor_sync(0xffffffffu, t, o);

    __shared__ double acc[6];
    if (lane == 0) acc[k] = t;
    __syncthreads();
    if (threadIdx.x == 0) {
        double loss = -acc[0] / acc[1];
        double semi = 0.5 * ((double)EE - acc[3]) * acc[2];   // SEMI_LAMBDA = 0.5
        double S    = acc[5];
        double edge = acc[4] / (S * S);                        // EDGE_LAMBDA^2 = 1
        out[0] = (float)(loss + semi + edge);
    }
}

extern "C" void kernel_launch(void* const* d_in, const int* in_sizes, int n_in,
                              void* d_out, int out_size) {
    const float*   pn    = (const float*)d_in[0];
    const float*   pe    = (const float*)d_in[1];
    const int*     gt    = (const int*)d_in[2];
    const uint8_t* mask  = (const uint8_t*)d_in[3];
    const int*     edges = (const int*)d_in[4];
    float* out = (float*)d_out;

    k_zero<<<1, 32>>>();
    k_main<<<GRID, 256>>>(pn, pe, gt, mask, edges);
    k_final<<<1, 192>>>(out);
}

// round 7
// speedup vs baseline: 1.4613x; 1.0158x over previous
#include <cuda_runtime.h>
#include <cstdint>

#define NN 1000000
#define EE 1000000
#define CC 64
#define ROW 65           // C+1 floats per poss_edge row
#define ROWB 260         // row stride in bytes
#define GRID 592         // 4 blocks/SM * 148 SMs -> single wave
#define NODE_B 64
#define SCALAR_B 160
#define GROUPS (EE / 4)  // 250000 groups of 4 edges
#define CHUNK 96         // groups per steal
#define NCHUNK ((GROUPS + CHUNK - 1) / CHUNK)

// Per-block partials: [block][0..5] = logp, maskN, sq, intr, raw, S
__device__ double g_part[GRID][6];
__device__ int g_counter;  // work-steal counter  (reset by last block each launch)
__device__ int g_done;     // arrival counter     (reset by last block each launch)

__global__ void __launch_bounds__(256, 4) k_main(
    const float* __restrict__ pn,
    const float* __restrict__ pe,
    const int* __restrict__ gt,
    const uint8_t* __restrict__ mask,
    const int* __restrict__ edges,
    float* __restrict__ out)
{
    const int bid = blockIdx.x;
    const int lane = threadIdx.x & 31;
    const int wib = threadIdx.x >> 5;
    const int2* __restrict__ edges2 = (const int2*)edges;
    const char* __restrict__ peb = (const char*)pe;

    float f_logp = 0.0f, f_intr = 0.0f, f_raw = 0.0f, f_sq = 0.0f;
    int i_mask = 0, i_S = 0;

    if (bid < NODE_B) {
        // ---- node loss: ILP-4 thread-per-node ----
        const int ltid = bid * 256 + threadIdx.x;
        const int lnth = NODE_B * 256;
        int i = ltid;
        for (; i + 3 * lnth < NN; i += 4 * lnth) {
            int idx[4]; unsigned m[4]; int g[4];
            #pragma unroll
            for (int j = 0; j < 4; j++) idx[j] = i + j * lnth;
            #pragma unroll
            for (int j = 0; j < 4; j++) m[j] = mask[idx[j]];
            #pragma unroll
            for (int j = 0; j < 4; j++) g[j] = gt[idx[j]];
            float p[4];
            #pragma unroll
            for (int j = 0; j < 4; j++)
                p[j] = m[j] ? __ldcs(&pn[(size_t)idx[j] * CC + g[j]]) : 1.0f;
            #pragma unroll
            for (int j = 0; j < 4; j++)
                if (m[j]) { f_logp += __logf(p[j]); i_mask++; }
        }
        for (; i < NN; i += lnth) {
            if (mask[i]) {
                f_logp += __logf(__ldcs(&pn[(size_t)i * CC + gt[i]]));
                i_mask++;
            }
        }
    } else if (bid < NODE_B + SCALAR_B) {
        // ---- per-edge scalar terms: ILP-4 thread-per-edge ----
        const int ltid = (bid - NODE_B) * 256 + threadIdx.x;
        const int lnth = SCALAR_B * 256;
        int e = ltid;
        for (; e + 3 * lnth < EE; e += 4 * lnth) {
            int ei[4]; int2 ev[4]; float pl[4];
            unsigned m0[4], m1[4]; int g0[4], g1[4];
            #pragma unroll
            for (int j = 0; j < 4; j++) ei[j] = e + j * lnth;
            #pragma unroll
            for (int j = 0; j < 4; j++) ev[j] = edges2[ei[j]];
            #pragma unroll
            for (int j = 0; j < 4; j++) pl[j] = pe[(size_t)ei[j] * ROW + CC];
            #pragma unroll
            for (int j = 0; j < 4; j++) { m0[j] = mask[ev[j].x]; m1[j] = mask[ev[j].y]; }
            #pragma unroll
            for (int j = 0; j < 4; j++) { g0[j] = gt[ev[j].x]; g1[j] = gt[ev[j].y]; }
            #pragma unroll
            for (int j = 0; j < 4; j++) {
                f_intr += pl[j];
                if (m0[j] | m1[j]) {
                    i_S++;
                    float c;
                    if (m0[j] & m1[j]) {
                        c = (g0[j] == g1[j])
                              ? __logf(pe[(size_t)ei[j] * ROW + g0[j]])
                              : __logf(pl[j]);
                    } else {
                        int g = m0[j] ? g0[j] : g1[j];
                        c = __logf(pl[j] + pe[(size_t)ei[j] * ROW + g]);
                    }
                    f_raw -= c;
                }
            }
        }
        for (; e < EE; e += lnth) {
            int2 ev = edges2[e];
            float pl = pe[(size_t)e * ROW + CC];
            f_intr += pl;
            unsigned m0 = mask[ev.x], m1 = mask[ev.y];
            if (m0 | m1) {
                i_S++;
                float c;
                if (m0 & m1) {
                    int ga = gt[ev.x], gb = gt[ev.y];
                    c = (ga == gb) ? __logf(pe[(size_t)e * ROW + ga]) : __logf(pl);
                } else {
                    int g = m0 ? gt[ev.x] : gt[ev.y];
                    c = __logf(pl + pe[(size_t)e * ROW + g]);
                }
                f_raw -= c;
            }
        }
    }

    // ---- sqdiff: warp-per-4-edges, work-stolen chunks, pipelined prefetch ----
    __shared__ int s_chunk;
    for (;;) {
        if (threadIdx.x == 0) s_chunk = atomicAdd(&g_counter, 1);
        __syncthreads();
        const int c = s_chunk;
        __syncthreads();
        if (c >= NCHUNK) break;
        const int gbeg = c * CHUNK;
        const int gend = (gbeg + CHUNK < GROUPS) ? gbeg + CHUNK : GROUPS;

        int g = gbeg + wib;
        if (g >= gend) continue;

        // prologue: prefetch first group's edges
        int2 evn[4];
        #pragma unroll
        for (int j = 0; j < 4; j++) evn[j] = __ldg(&edges2[g * 4 + j]);

        while (g < gend) {
            int2 ev[4];
            #pragma unroll
            for (int j = 0; j < 4; j++) ev[j] = evn[j];
            const int gn = g + 8;

            // 32-bit byte offsets into the row table
            unsigned oa[4], ob[4];
            #pragma unroll
            for (int j = 0; j < 4; j++) {
                oa[j] = (unsigned)ev[j].x * ROWB;
                ob[j] = (unsigned)ev[j].y * ROWB;
            }

            // issue all 16 gather loads before consuming any
            float va[4], wa[4], vb[4], wb[4];
            #pragma unroll
            for (int j = 0; j < 4; j++) {
                const float* ra = (const float*)(peb + oa[j]);
                const float* rb = (const float*)(peb + ob[j]);
                va[j] = ra[lane];
                wa[j] = ra[lane + 32];
                vb[j] = rb[lane];
                wb[j] = rb[lane + 32];
            }
            // col-64 residual: lane j handles edge j (L1 hits: same lines)
            float ca = 0.0f, cb = 0.0f;
            if (lane < 4) {
                ca = *(const float*)(peb + oa[lane] + CC * 4);
                cb = *(const float*)(peb + ob[lane] + CC * 4);
            }

            // prefetch NEXT group's edges while the 18 loads above are in flight
            if (gn < gend) {
                #pragma unroll
                for (int j = 0; j < 4; j++) evn[j] = __ldg(&edges2[gn * 4 + j]);
            }

            float s = 0.0f;
            #pragma unroll
            for (int j = 0; j < 4; j++) {
                float d0 = va[j] - vb[j];
                float d1 = wa[j] - wb[j];
                s += d0 * d0 + d1 * d1;
            }
            if (lane < 4) {
                float d2 = ca - cb;
                s += d2 * d2;
            }
            f_sq += s;
            g = gn;
        }
    }

    // ---- block reduction -> per-block partial slot (no atomics) ----
    double vals[6] = {(double)f_logp, (double)i_mask, (double)f_sq,
                      (double)f_intr, (double)f_raw,  (double)i_S};
    #pragma unroll
    for (int k = 0; k < 6; k++) {
        double v = vals[k];
        #pragma unroll
        for (int o = 16; o; o >>= 1) v += __shfl_xor_sync(0xffffffffu, v, o);
        vals[k] = v;
    }
    __shared__ double sh[8][6];
    if (lane == 0) {
        #pragma unroll
        for (int k = 0; k < 6; k++) sh[wib][k] = vals[k];
    }
    __syncthreads();
    if (threadIdx.x < 6) {
        double t = 0.0;
        #pragma unroll
        for (int w = 0; w < 8; w++) t += sh[w][threadIdx.x];
        g_part[bid][threadIdx.x] = t;
    }

    // ---- last-block finalize (threadFenceReduction pattern) ----
    __threadfence();
    __syncthreads();
    __shared__ bool s_last;
    if (threadIdx.x == 0) {
        int prev = atomicAdd(&g_done, 1);
        s_last = (prev == GRID - 1);
    }
    __syncthreads();
    if (!s_last) return;

    __threadfence();  // order: see all g_part writes from other blocks
    if (threadIdx.x == 0) {
        g_done = 0;      // reset for next graph replay -- all blocks have
        g_counter = 0;   // finished stealing, so this cannot race
    }

    // warp k (k<6) reduces accumulator k over all blocks
    const int k = wib;
    __shared__ double acc[6];
    if (k < 6) {
        double t = 0.0;
        for (int b = lane; b < GRID; b += 32) t += g_part[b][k];
        #pragma unroll
        for (int o = 16; o; o >>= 1) t += __shfl_xor_sync(0xffffffffu, t, o);
        if (lane == 0) acc[k] = t;
    }
    __syncthreads();
    if (threadIdx.x == 0) {
        double loss = -acc[0] / acc[1];
        double semi = 0.5 * ((double)EE - acc[3]) * acc[2];   // SEMI_LAMBDA = 0.5
        double S    = acc[5];
        double edge = acc[4] / (S * S);                        // EDGE_LAMBDA^2 = 1
        out[0] = (float)(loss + semi + edge);
    }
}

extern "C" void kernel_launch(void* const* d_in, const int* in_sizes, int n_in,
                              void* d_out, int out_size) {
    const float*   pn    = (const float*)d_in[0];
    const float*   pe    = (const float*)d_in[1];
    const int*     gt    = (const int*)d_in[2];
    const uint8_t* mask  = (const uint8_t*)d_in[3];
    const int*     edges = (const int*)d_in[4];
    float* out = (float*)d_out;

    k_main<<<GRID, 256>>>(pn, pe, gt, mask, edges, out);
}

// round 8
// speedup vs baseline: 1.5385x; 1.0528x over previous
#include <cuda_runtime.h>
#include <cstdint>

#define NN 1000000
#define EE 1000000
#define CC 64
#define ROW 65           // C+1 floats per poss_edge row
#define ROWB 260         // row stride in bytes
#define GRID 592         // 4 blocks/SM * 148 SMs -> single wave
#define NODE_B 64
#define SCALAR_B 160
#define GROUPS (EE / 4)  // 250000 groups of 4 edges
#define WCHUNK 16        // groups per warp-steal
#define NCHUNKW ((GROUPS + WCHUNK - 1) / WCHUNK)

// Per-block partials: [block][0..5] = logp, maskN, sq, intr, raw, S
__device__ double g_part[GRID][6];
__device__ int g_counter;  // warp work-steal counter (reset by last block)
__device__ int g_done;     // arrival counter         (reset by last block)

__global__ void __launch_bounds__(256, 4) k_main(
    const float* __restrict__ pn,
    const float* __restrict__ pe,
    const int* __restrict__ gt,
    const uint8_t* __restrict__ mask,
    const int* __restrict__ edges,
    float* __restrict__ out)
{
    const int bid = blockIdx.x;
    const int lane = threadIdx.x & 31;
    const int wib = threadIdx.x >> 5;
    const int2* __restrict__ edges2 = (const int2*)edges;
    const char* __restrict__ peb = (const char*)pe;

    float f_logp = 0.0f, f_intr = 0.0f, f_raw = 0.0f, f_sq = 0.0f;
    int i_mask = 0, i_S = 0;

    if (bid < NODE_B) {
        // ---- node loss: ILP-4 thread-per-node ----
        const int ltid = bid * 256 + threadIdx.x;
        const int lnth = NODE_B * 256;
        int i = ltid;
        for (; i + 3 * lnth < NN; i += 4 * lnth) {
            int idx[4]; unsigned m[4]; int g[4];
            #pragma unroll
            for (int j = 0; j < 4; j++) idx[j] = i + j * lnth;
            #pragma unroll
            for (int j = 0; j < 4; j++) m[j] = mask[idx[j]];
            #pragma unroll
            for (int j = 0; j < 4; j++) g[j] = gt[idx[j]];
            float p[4];
            #pragma unroll
            for (int j = 0; j < 4; j++)
                p[j] = m[j] ? __ldcs(&pn[(size_t)idx[j] * CC + g[j]]) : 1.0f;
            #pragma unroll
            for (int j = 0; j < 4; j++)
                if (m[j]) { f_logp += __logf(p[j]); i_mask++; }
        }
        for (; i < NN; i += lnth) {
            if (mask[i]) {
                f_logp += __logf(__ldcs(&pn[(size_t)i * CC + gt[i]]));
                i_mask++;
            }
        }
    } else if (bid < NODE_B + SCALAR_B) {
        // ---- per-edge scalar terms: ILP-4 thread-per-edge ----
        const int ltid = (bid - NODE_B) * 256 + threadIdx.x;
        const int lnth = SCALAR_B * 256;
        int e = ltid;
        for (; e + 3 * lnth < EE; e += 4 * lnth) {
            int ei[4]; int2 ev[4]; float pl[4];
            unsigned m0[4], m1[4]; int g0[4], g1[4];
            #pragma unroll
            for (int j = 0; j < 4; j++) ei[j] = e + j * lnth;
            #pragma unroll
            for (int j = 0; j < 4; j++) ev[j] = edges2[ei[j]];
            #pragma unroll
            for (int j = 0; j < 4; j++) pl[j] = pe[(size_t)ei[j] * ROW + CC];
            #pragma unroll
            for (int j = 0; j < 4; j++) { m0[j] = mask[ev[j].x]; m1[j] = mask[ev[j].y]; }
            #pragma unroll
            for (int j = 0; j < 4; j++) { g0[j] = gt[ev[j].x]; g1[j] = gt[ev[j].y]; }
            #pragma unroll
            for (int j = 0; j < 4; j++) {
                f_intr += pl[j];
                if (m0[j] | m1[j]) {
                    i_S++;
                    float c;
                    if (m0[j] & m1[j]) {
                        c = (g0[j] == g1[j])
                              ? __logf(pe[(size_t)ei[j] * ROW + g0[j]])
                              : __logf(pl[j]);
                    } else {
                        int g = m0[j] ? g0[j] : g1[j];
                        c = __logf(pl[j] + pe[(size_t)ei[j] * ROW + g]);
                    }
                    f_raw -= c;
                }
            }
        }
        for (; e < EE; e += lnth) {
            int2 ev = edges2[e];
            float pl = pe[(size_t)e * ROW + CC];
            f_intr += pl;
            unsigned m0 = mask[ev.x], m1 = mask[ev.y];
            if (m0 | m1) {
                i_S++;
                float c;
                if (m0 & m1) {
                    int ga = gt[ev.x], gb = gt[ev.y];
                    c = (ga == gb) ? __logf(pe[(size_t)e * ROW + ga]) : __logf(pl);
                } else {
                    int g = m0 ? gt[ev.x] : gt[ev.y];
                    c = __logf(pl + pe[(size_t)e * ROW + g]);
                }
                f_raw -= c;
            }
        }
    }

    // ---- sqdiff: warp-per-4-edges, WARP-level work stealing (no barriers),
    //      pipelined edge prefetch ----
    for (;;) {
        int c;
        if (lane == 0) c = atomicAdd(&g_counter, 1);
        c = __shfl_sync(0xffffffffu, c, 0);
        if (c >= NCHUNKW) break;
        const int gbeg = c * WCHUNK;
        const int gend = (gbeg + WCHUNK < GROUPS) ? gbeg + WCHUNK : GROUPS;

        // prologue: prefetch first group's edges
        int2 evn[4];
        #pragma unroll
        for (int j = 0; j < 4; j++) evn[j] = __ldg(&edges2[gbeg * 4 + j]);

        for (int g = gbeg; g < gend; g++) {
            int2 ev[4];
            #pragma unroll
            for (int j = 0; j < 4; j++) ev[j] = evn[j];

            // 32-bit byte offsets into the row table
            unsigned oa[4], ob[4];
            #pragma unroll
            for (int j = 0; j < 4; j++) {
                oa[j] = (unsigned)ev[j].x * ROWB;
                ob[j] = (unsigned)ev[j].y * ROWB;
            }

            // issue all 16 gather loads before consuming any
            float va[4], wa[4], vb[4], wb[4];
            #pragma unroll
            for (int j = 0; j < 4; j++) {
                const float* ra = (const float*)(peb + oa[j]);
                const float* rb = (const float*)(peb + ob[j]);
                va[j] = ra[lane];
                wa[j] = ra[lane + 32];
                vb[j] = rb[lane];
                wb[j] = rb[lane + 32];
            }
            // col-64 residual: lane j handles edge j
            float ca = 0.0f, cb = 0.0f;
            if (lane < 4) {
                ca = *(const float*)(peb + oa[lane] + CC * 4);
                cb = *(const float*)(peb + ob[lane] + CC * 4);
            }

            // prefetch NEXT group's edges while the 18 loads above are in flight
            if (g + 1 < gend) {
                #pragma unroll
                for (int j = 0; j < 4; j++) evn[j] = __ldg(&edges2[(g + 1) * 4 + j]);
            }

            float s = 0.0f;
            #pragma unroll
            for (int j = 0; j < 4; j++) {
                float d0 = va[j] - vb[j];
                float d1 = wa[j] - wb[j];
                s += d0 * d0 + d1 * d1;
            }
            if (lane < 4) {
                float d2 = ca - cb;
                s += d2 * d2;
            }
            f_sq += s;
        }
    }

    // ---- block reduction -> per-block partial slot (no atomics) ----
    double vals[6] = {(double)f_logp, (double)i_mask, (double)f_sq,
                      (double)f_intr, (double)f_raw,  (double)i_S};
    #pragma unroll
    for (int k = 0; k < 6; k++) {
        double v = vals[k];
        #pragma unroll
        for (int o = 16; o; o >>= 1) v += __shfl_xor_sync(0xffffffffu, v, o);
        vals[k] = v;
    }
    __shared__ double sh[8][6];
    if (lane == 0) {
        #pragma unroll
        for (int k = 0; k < 6; k++) sh[wib][k] = vals[k];
    }
    __syncthreads();
    if (threadIdx.x < 6) {
        double t = 0.0;
        #pragma unroll
        for (int w = 0; w < 8; w++) t += sh[w][threadIdx.x];
        g_part[bid][threadIdx.x] = t;
    }

    // ---- last-block finalize (threadFenceReduction pattern) ----
    __threadfence();
    __syncthreads();
    __shared__ bool s_last;
    if (threadIdx.x == 0) {
        int prev = atomicAdd(&g_done, 1);
        s_last = (prev == GRID - 1);
    }
    __syncthreads();
    if (!s_last) return;

    __threadfence();  // order: see all g_part writes from other blocks
    if (threadIdx.x == 0) {
        g_done = 0;      // reset for next graph replay -- all blocks have
        g_counter = 0;   // finished stealing, so this cannot race
    }

    // warp k (k<6) reduces accumulator k over all blocks
    const int k = wib;
    __shared__ double acc[6];
    if (k < 6) {
        double t = 0.0;
        for (int b = lane; b < GRID; b += 32) t += g_part[b][k];
        #pragma unroll
        for (int o = 16; o; o >>= 1) t += __shfl_xor_sync(0xffffffffu, t, o);
        if (lane == 0) acc[k] = t;
    }
    __syncthreads();
    if (threadIdx.x == 0) {
        double loss = -acc[0] / acc[1];
        double semi = 0.5 * ((double)EE - acc[3]) * acc[2];   // SEMI_LAMBDA = 0.5
        double S    = acc[5];
        double edge = acc[4] / (S * S);                        // EDGE_LAMBDA^2 = 1
        out[0] = (float)(loss + semi + edge);
    }
}

extern "C" void kernel_launch(void* const* d_in, const int* in_sizes, int n_in,
                              void* d_out, int out_size) {
    const float*   pn    = (const float*)d_in[0];
    const float*   pe    = (const float*)d_in[1];
    const int*     gt    = (const int*)d_in[2];
    const uint8_t* mask  = (const uint8_t*)d_in[3];
    const int*     edges = (const int*)d_in[4];
    float* out = (float*)d_out;

    k_main<<<GRID, 256>>>(pn, pe, gt, mask, edges, out);
}